// round 3
// baseline (speedup 1.0000x reference)
#include <cuda_runtime.h>
#include <math.h>

#define B_ 64
#define T_ 1024
#define E_ 512
#define H_ 256
#define M_ (B_*T_)          // 65536
#define RREG 128            // W row elements kept in registers (rest in smem)

// ---------------- scratch (device globals; no allocation allowed) ----------------
__device__ float g_x0[(size_t)M_*E_];          // embedded input        [M,512]
__device__ float g_xp[(size_t)2*T_*B_*H_];     // per-layer projections [2][T][B][H]
__device__ float g_x1[(size_t)M_*512];         // layer0 output concat  [M,512]
__device__ float g_x2[(size_t)M_*512];         // layer1 output concat  [M,512]
__device__ float g_xph[(size_t)T_*B_*16];      // head projections      [T][B][16] (13 used)

// ---------------- packed f32x2 FMA (Blackwell) ----------------
__device__ __forceinline__ void ffma2(float2 &acc, float2 a, float2 b) {
    asm("fma.rn.f32x2 %0, %1, %2, %0;"
        : "+l"(reinterpret_cast<unsigned long long&>(acc))
        : "l"(reinterpret_cast<unsigned long long&>(a)),
          "l"(reinterpret_cast<unsigned long long&>(b)));
}

// ---------------- 1) embedding gather ----------------
__global__ void embed_kernel(const int* __restrict__ tokens,
                             const float* __restrict__ emb) {
    int idx = blockIdx.x * 256 + threadIdx.x;   // float4 index, total M_*128
    int m   = idx >> 7;
    int e4  = idx & 127;
    int tok = __ldg(&tokens[m]);
    reinterpret_cast<float4*>(g_x0)[idx] =
        reinterpret_cast<const float4*>(emb + (size_t)tok * E_)[e4];
}

// ---------------- 2) input projection GEMM ----------------
// C[m,n] = sum_k A[m,k] * W[n,k] + bih[n] + bhh[n], written to
// g_xp[d][t][b][h] with d=n>>8, h=n&255, b=m>>10, t=m&1023.
__global__ __launch_bounds__(256) void gemm_xp_kernel(
    int which_A,                       // 0: g_x0, 1: g_x1
    const float* __restrict__ W,       // [512,512]
    const float* __restrict__ bih,     // [512]
    const float* __restrict__ bhh)     // [512]
{
    __shared__ float As[8][128];
    __shared__ float Bs[8][128];
    const float* A = which_A ? g_x1 : g_x0;

    int tid = threadIdx.x;
    int m0 = blockIdx.x * 128;
    int n0 = blockIdx.y * 128;
    int lr = tid >> 1, lh = tid & 1;
    const float* Ap = A + (size_t)(m0 + lr) * 512 + lh * 4;
    const float* Wp = W + (size_t)(n0 + lr) * 512 + lh * 4;
    int ty = tid >> 4, tx = tid & 15;

    float2 acc[8][4];
#pragma unroll
    for (int i = 0; i < 8; i++)
#pragma unroll
        for (int j = 0; j < 4; j++) acc[i][j] = make_float2(0.f, 0.f);

    float4 av = *(const float4*)Ap;
    float4 wv = *(const float4*)Wp;

    for (int k0 = 0; k0 < 512; k0 += 8) {
        __syncthreads();
        As[lh*4+0][lr] = av.x; As[lh*4+1][lr] = av.y;
        As[lh*4+2][lr] = av.z; As[lh*4+3][lr] = av.w;
        Bs[lh*4+0][lr] = wv.x; Bs[lh*4+1][lr] = wv.y;
        Bs[lh*4+2][lr] = wv.z; Bs[lh*4+3][lr] = wv.w;
        __syncthreads();
        if (k0 + 8 < 512) {                     // prefetch next tile
            av = *(const float4*)(Ap + k0 + 8);
            wv = *(const float4*)(Wp + k0 + 8);
        }
#pragma unroll
        for (int kk = 0; kk < 8; kk++) {
            float a[8];
            *(float4*)&a[0] = *(const float4*)&As[kk][ty*8];
            *(float4*)&a[4] = *(const float4*)&As[kk][ty*8+4];
            float4 b0 = *(const float4*)&Bs[kk][tx*8];
            float4 b1 = *(const float4*)&Bs[kk][tx*8+4];
            float2 bp[4] = { make_float2(b0.x,b0.y), make_float2(b0.z,b0.w),
                             make_float2(b1.x,b1.y), make_float2(b1.z,b1.w) };
#pragma unroll
            for (int i = 0; i < 8; i++) {
                float2 ap = make_float2(a[i], a[i]);
#pragma unroll
                for (int j = 0; j < 4; j++) ffma2(acc[i][j], ap, bp[j]);
            }
        }
    }

#pragma unroll
    for (int i = 0; i < 8; i++) {
        int m = m0 + ty*8 + i;
        int bb = m >> 10, t = m & 1023;
#pragma unroll
        for (int p = 0; p < 2; p++) {
            int n = n0 + tx*8 + p*4;
            int d = n >> 8, h = n & 255;
            float4 v;
            v.x = acc[i][p*2  ].x + bih[n  ] + bhh[n  ];
            v.y = acc[i][p*2  ].y + bih[n+1] + bhh[n+1];
            v.z = acc[i][p*2+1].x + bih[n+2] + bhh[n+2];
            v.w = acc[i][p*2+1].y + bih[n+3] + bhh[n+3];
            *(float4*)&g_xp[(((size_t)d*T_ + t)*B_ + bb)*H_ + h] = v;
        }
    }
}

// ---------------- 3) bidirectional RNN recurrence ----------------
// One CTA per (batch, dir). 256 threads; thread j computes output channel j.
// W row j: first RREG elems in registers, rest transposed in shared memory.
__global__ __launch_bounds__(256, 1) void rnn_layer_kernel(
    const float* __restrict__ whh,     // [2][H][H] (this layer)
    int which_out)                     // 0 -> g_x1, 1 -> g_x2
{
    extern __shared__ float sm[];
    float* Wt  = sm;                         // [(256-RREG)][256]
    float* hsh = sm + (256 - RREG) * 256;    // [256]
    float* xnext = which_out ? g_x2 : g_x1;

    int tid = threadIdx.x;
    int d = blockIdx.x & 1;
    int b = blockIdx.x >> 1;
    const float* Wd = whh + (size_t)d * H_ * H_;

    float wreg[RREG];
#pragma unroll
    for (int i = 0; i < RREG; i++) wreg[i] = Wd[(size_t)tid * H_ + i];

    for (int idx = tid; idx < (256 - RREG) * 256; idx += 256) {
        int i = idx >> 8;          // 0..(255-RREG)
        int j = idx & 255;
        Wt[idx] = Wd[(size_t)j * H_ + (RREG + i)];   // transposed
    }
    hsh[tid] = 0.f;
    __syncthreads();

    const float* xpd = g_xp + (size_t)d * T_ * B_ * H_;
    float* outp = xnext + (size_t)b * T_ * 512 + d * H_ + tid;

    int t = d ? (T_ - 1) : 0;
    int step = d ? -1 : 1;
    float xv = xpd[((size_t)t * B_ + b) * H_ + tid];

    for (int s = 0; s < T_; ++s) {
        int tn = t + step;
        float xnv = 0.f;
        if (s + 1 < T_) xnv = xpd[((size_t)tn * B_ + b) * H_ + tid];  // prefetch

        float acc = xv;
#pragma unroll
        for (int i = 0; i < RREG; i += 4) {
            float4 h4 = *(const float4*)&hsh[i];
            acc += h4.x*wreg[i] + h4.y*wreg[i+1] + h4.z*wreg[i+2] + h4.w*wreg[i+3];
        }
#pragma unroll 8
        for (int i = RREG; i < 256; i += 4) {
            float4 h4 = *(const float4*)&hsh[i];
            int r = i - RREG;
            acc += h4.x * Wt[(r  )*256 + tid]
                 + h4.y * Wt[(r+1)*256 + tid]
                 + h4.z * Wt[(r+2)*256 + tid]
                 + h4.w * Wt[(r+3)*256 + tid];
        }
        float hn = tanhf(acc);
        __syncthreads();                 // all reads of old h done
        hsh[tid] = hn;
        outp[(size_t)t * 512] = hn;
        __syncthreads();                 // new h visible
        xv = xnv;
        t = tn;
    }
}

// ---------------- 4) head projections: relu(x2) @ [13x512]^T + biases ----------------
__global__ __launch_bounds__(256) void head_xp_kernel(
    const float* __restrict__ wi, const float* __restrict__ bi_ih, const float* __restrict__ bi_hh,
    const float* __restrict__ wf, const float* __restrict__ bf_ih, const float* __restrict__ bf_hh,
    const float* __restrict__ wc, const float* __restrict__ bc_ih, const float* __restrict__ bc_hh)
{
    __shared__ float Ws[13 * 512];
    __shared__ float bs[13];
    int tid = threadIdx.x;
    for (int idx = tid; idx < 13 * 512; idx += 256) {
        int n = idx / 512, k = idx % 512;
        float w;
        if (n < 3)      w = wi[n*512 + k];
        else if (n < 8) w = wf[(n-3)*512 + k];
        else            w = wc[(n-8)*512 + k];
        Ws[idx] = w;
    }
    if (tid < 13) {
        float bv;
        if (tid < 3)      bv = bi_ih[tid]   + bi_hh[tid];
        else if (tid < 8) bv = bf_ih[tid-3] + bf_hh[tid-3];
        else              bv = bc_ih[tid-8] + bc_hh[tid-8];
        bs[tid] = bv;
    }
    __syncthreads();

    int w = tid >> 5, lane = tid & 31;
    int m = blockIdx.x * 8 + w;
    const float* xr = g_x2 + (size_t)m * 512;

    float acc[13];
#pragma unroll
    for (int n = 0; n < 13; n++) acc[n] = 0.f;

    for (int i = 0; i < 16; i++) {
        int k = i * 32 + lane;
        float xv = xr[k];
        xv = xv > 0.f ? xv : 0.f;
#pragma unroll
        for (int n = 0; n < 13; n++) acc[n] += xv * Ws[n*512 + k];
    }
#pragma unroll
    for (int n = 0; n < 13; n++) {
#pragma unroll
        for (int off = 16; off; off >>= 1)
            acc[n] += __shfl_xor_sync(0xffffffff, acc[n], off);
    }
    if (lane == 0) {
        int bb = m >> 10, t = m & 1023;
        float* o = g_xph + ((size_t)t * B_ + bb) * 16;
#pragma unroll
        for (int n = 0; n < 13; n++) o[n] = acc[n] + bs[n];
    }
}

// ---------------- 5) head recurrences (3 tiny forward scans) ----------------
__global__ void head_rnn_kernel(
    const float* __restrict__ wi_hh,
    const float* __restrict__ wf_hh,
    const float* __restrict__ wc_hh,
    float* __restrict__ out)
{
    int hid = blockIdx.x % 3;
    int b   = blockIdx.x / 3;
    int lane = threadIdx.x;
    int C, off;
    size_t outoff;
    const float* Whh;
    if (hid == 0)      { C = 3; off = 0; outoff = 0;                         Whh = wi_hh; }
    else if (hid == 1) { C = 5; off = 3; outoff = (size_t)B_*T_*3;           Whh = wf_hh; }
    else               { C = 5; off = 8; outoff = (size_t)B_*T_*3 + (size_t)B_*T_*5; Whh = wc_hh; }

    float w[5] = {0,0,0,0,0};
    if (lane < C)
        for (int k = 0; k < C; k++) w[k] = Whh[lane*C + k];

    float h = 0.f;
    float* ob = out + outoff + (size_t)b * T_ * C;
    for (int t = 0; t < T_; t++) {
        float xv = (lane < C) ? g_xph[((size_t)t * B_ + b) * 16 + off + lane] : 0.f;
        float h0 = __shfl_sync(0xffffffff, h, 0);
        float h1 = __shfl_sync(0xffffffff, h, 1);
        float h2 = __shfl_sync(0xffffffff, h, 2);
        float h3 = __shfl_sync(0xffffffff, h, 3);
        float h4 = __shfl_sync(0xffffffff, h, 4);
        float acc = xv + h0*w[0] + h1*w[1] + h2*w[2] + h3*w[3] + h4*w[4];
        h = tanhf(acc);
        if (lane < C) ob[(size_t)t * C + lane] = h;
    }
}

// ---------------- launch ----------------
extern "C" void kernel_launch(void* const* d_in, const int* in_sizes, int n_in,
                              void* d_out, int out_size) {
    const int*   tokens = (const int*)  d_in[0];
    const float* emb    = (const float*)d_in[1];
    const float* w_ih   = (const float*)d_in[2];   // [2][2][256][512]
    const float* w_hh   = (const float*)d_in[3];   // [2][2][256][256]
    const float* b_ih   = (const float*)d_in[4];   // [2][2][256]
    const float* b_hh   = (const float*)d_in[5];
    const float* iw_ih  = (const float*)d_in[6];
    const float* iw_hh  = (const float*)d_in[7];
    const float* ib_ih  = (const float*)d_in[8];
    const float* ib_hh  = (const float*)d_in[9];
    const float* fw_ih  = (const float*)d_in[10];
    const float* fw_hh  = (const float*)d_in[11];
    const float* fb_ih  = (const float*)d_in[12];
    const float* fb_hh  = (const float*)d_in[13];
    const float* cw_ih  = (const float*)d_in[14];
    const float* cw_hh  = (const float*)d_in[15];
    const float* cb_ih  = (const float*)d_in[16];
    const float* cb_hh  = (const float*)d_in[17];
    float* out = (float*)d_out;

    const int rnn_smem = (256 - RREG) * 256 * 4 + 256 * 4;
    cudaFuncSetAttribute(rnn_layer_kernel,
                         cudaFuncAttributeMaxDynamicSharedMemorySize, rnn_smem);

    // 1) gather embeddings
    embed_kernel<<<(M_ * (E_/4)) / 256, 256>>>(tokens, emb);

    // 2) layer 0: projection + scan
    gemm_xp_kernel<<<dim3(M_/128, 512/128), 256>>>(0, w_ih, b_ih, b_hh);
    rnn_layer_kernel<<<B_ * 2, 256, rnn_smem>>>(w_hh, 0);

    // 3) layer 1: projection + scan
    gemm_xp_kernel<<<dim3(M_/128, 512/128), 256>>>(1, w_ih + 2*H_*E_,
                                                   b_ih + 2*H_, b_hh + 2*H_);
    rnn_layer_kernel<<<B_ * 2, 256, rnn_smem>>>(w_hh + 2*H_*H_, 1);

    // 4) head projections (with ReLU on the fly)
    head_xp_kernel<<<M_/8, 256>>>(iw_ih, ib_ih, ib_hh,
                                  fw_ih, fb_ih, fb_hh,
                                  cw_ih, cb_ih, cb_hh);

    // 5) head scans -> final output
    head_rnn_kernel<<<B_ * 3, 32>>>(iw_hh, fw_hh, cw_hh, out);
}

// round 4
// speedup vs baseline: 1.1518x; 1.1518x over previous
#include <cuda_runtime.h>
#include <math.h>

#define B_ 64
#define T_ 1024
#define E_ 512
#define H_ 256
#define M_ (B_*T_)          // 65536

// RNN recurrence decomposition: 512 threads, 2 threads per output channel.
// Each thread owns 128 W elements: 96 in registers (48 float2) + 32 in smem (16 float2).
#define WREG2 48            // float2 weights in registers per thread
#define WSH2  16            // float2 weights in shared per thread

// ---------------- scratch (device globals; no allocation allowed) ----------------
__device__ float g_x0[(size_t)M_*E_];          // embedded input        [M,512]
__device__ float g_xp[(size_t)2*T_*B_*H_];     // per-layer projections [2][T][B][H]
__device__ float g_x1[(size_t)M_*512];         // layer0 output concat  [M,512]
__device__ float g_x2[(size_t)M_*512];         // layer1 output concat  [M,512]
__device__ float g_xph[(size_t)T_*B_*16];      // head projections      [T][B][16] (13 used)

// ---------------- packed f32x2 FMA (Blackwell) ----------------
__device__ __forceinline__ void ffma2(float2 &acc, float2 a, float2 b) {
    asm("fma.rn.f32x2 %0, %1, %2, %0;"
        : "+l"(reinterpret_cast<unsigned long long&>(acc))
        : "l"(reinterpret_cast<unsigned long long&>(a)),
          "l"(reinterpret_cast<unsigned long long&>(b)));
}

// ---------------- 1) embedding gather ----------------
__global__ void embed_kernel(const int* __restrict__ tokens,
                             const float* __restrict__ emb) {
    int idx = blockIdx.x * 256 + threadIdx.x;   // float4 index, total M_*128
    int m   = idx >> 7;
    int e4  = idx & 127;
    int tok = __ldg(&tokens[m]);
    reinterpret_cast<float4*>(g_x0)[idx] =
        reinterpret_cast<const float4*>(emb + (size_t)tok * E_)[e4];
}

// ---------------- 2) input projection GEMM ----------------
// C[m,n] = sum_k A[m,k] * W[n,k] + bih[n] + bhh[n], written to
// g_xp[d][t][b][h] with d=n>>8, h=n&255, b=m>>10, t=m&1023.
__global__ __launch_bounds__(256, 2) void gemm_xp_kernel(
    int which_A,                       // 0: g_x0, 1: g_x1
    const float* __restrict__ W,       // [512,512]
    const float* __restrict__ bih,     // [512]
    const float* __restrict__ bhh)     // [512]
{
    __shared__ float As[8][128];
    __shared__ float Bs[8][128];
    const float* A = which_A ? g_x1 : g_x0;

    int tid = threadIdx.x;
    int m0 = blockIdx.x * 128;
    int n0 = blockIdx.y * 128;
    int lr = tid >> 1, lh = tid & 1;
    const float* Ap = A + (size_t)(m0 + lr) * 512 + lh * 4;
    const float* Wp = W + (size_t)(n0 + lr) * 512 + lh * 4;
    int ty = tid >> 4, tx = tid & 15;

    float2 acc[8][4];
#pragma unroll
    for (int i = 0; i < 8; i++)
#pragma unroll
        for (int j = 0; j < 4; j++) acc[i][j] = make_float2(0.f, 0.f);

    float4 av = *(const float4*)Ap;
    float4 wv = *(const float4*)Wp;

    for (int k0 = 0; k0 < 512; k0 += 8) {
        __syncthreads();
        As[lh*4+0][lr] = av.x; As[lh*4+1][lr] = av.y;
        As[lh*4+2][lr] = av.z; As[lh*4+3][lr] = av.w;
        Bs[lh*4+0][lr] = wv.x; Bs[lh*4+1][lr] = wv.y;
        Bs[lh*4+2][lr] = wv.z; Bs[lh*4+3][lr] = wv.w;
        __syncthreads();
        if (k0 + 8 < 512) {                     // prefetch next tile
            av = *(const float4*)(Ap + k0 + 8);
            wv = *(const float4*)(Wp + k0 + 8);
        }
#pragma unroll
        for (int kk = 0; kk < 8; kk++) {
            float a[8];
            *(float4*)&a[0] = *(const float4*)&As[kk][ty*8];
            *(float4*)&a[4] = *(const float4*)&As[kk][ty*8+4];
            float4 b0 = *(const float4*)&Bs[kk][tx*8];
            float4 b1 = *(const float4*)&Bs[kk][tx*8+4];
            float2 bp[4] = { make_float2(b0.x,b0.y), make_float2(b0.z,b0.w),
                             make_float2(b1.x,b1.y), make_float2(b1.z,b1.w) };
#pragma unroll
            for (int i = 0; i < 8; i++) {
                float2 ap = make_float2(a[i], a[i]);
#pragma unroll
                for (int j = 0; j < 4; j++) ffma2(acc[i][j], ap, bp[j]);
            }
        }
    }

#pragma unroll
    for (int i = 0; i < 8; i++) {
        int m = m0 + ty*8 + i;
        int bb = m >> 10, t = m & 1023;
#pragma unroll
        for (int p = 0; p < 2; p++) {
            int n = n0 + tx*8 + p*4;
            int d = n >> 8, h = n & 255;
            float4 v;
            v.x = acc[i][p*2  ].x + bih[n  ] + bhh[n  ];
            v.y = acc[i][p*2  ].y + bih[n+1] + bhh[n+1];
            v.z = acc[i][p*2+1].x + bih[n+2] + bhh[n+2];
            v.w = acc[i][p*2+1].y + bih[n+3] + bhh[n+3];
            *(float4*)&g_xp[(((size_t)d*T_ + t)*B_ + bb)*H_ + h] = v;
        }
    }
}

// ---------------- 3) bidirectional RNN recurrence ----------------
// One CTA per (batch, dir). 512 threads; thread pair (j, j+256) computes
// output channel j: thread half=tid>>8 covers h[half*128 : half*128+128].
// 96 weights/thread in registers (f32x2 FMA), 32 from smem (transposed).
__global__ __launch_bounds__(512, 1) void rnn_layer_kernel(
    const float* __restrict__ whh,     // [2][H][H] (this layer)
    int which_out)                     // 0 -> g_x1, 1 -> g_x2
{
    extern __shared__ float sm[];
    float2* Wt2     = (float2*)sm;                 // [WSH2][512]
    float*  hsh     = sm + WSH2 * 512 * 2;         // [256]
    float*  partial = hsh + 256;                   // [512]
    float*  xnext   = which_out ? g_x2 : g_x1;

    int tid  = threadIdx.x;
    int half = tid >> 8;          // 0 or 1
    int j    = tid & 255;         // output channel
    int d = blockIdx.x & 1;
    int b = blockIdx.x >> 1;
    const float* Wd = whh + (size_t)d * H_ * H_;

    // register weights: W[j][half*128 + 2k], k=0..47
    float2 wreg2[WREG2];
    {
        const float2* wrow = (const float2*)(Wd + (size_t)j * H_ + half * 128);
#pragma unroll
        for (int k = 0; k < WREG2; k++) wreg2[k] = wrow[k];
    }
    // shared weights, transposed: Wt2[kk][tid] = W[j][half*128 + 96 + 2kk]
    for (int idx = tid; idx < WSH2 * 512; idx += 512) {
        int kk = idx >> 9;
        int t2 = idx & 511;
        int j2 = t2 & 255, h2 = t2 >> 8;
        Wt2[idx] = *(const float2*)(Wd + (size_t)j2 * H_ + h2 * 128 + 2*WREG2 + 2 * kk);
    }
    if (tid < 256) hsh[tid] = 0.f;
    __syncthreads();

    const float* xpd = g_xp + (size_t)d * T_ * B_ * H_;
    float* outp = xnext + (size_t)b * T_ * 512 + d * H_ + j;

    int t = d ? (T_ - 1) : 0;
    int step = d ? -1 : 1;

    float xv = 0.f, xnv = 0.f;
    if (tid < 256) {
        xv  = xpd[((size_t)t * B_ + b) * H_ + j];
        xnv = xpd[((size_t)(t + step) * B_ + b) * H_ + j];
    }

    const float4* h4p = (const float4*)(hsh + half * 128);

    for (int s = 0; s < T_; ++s) {
        float xfut = 0.f;
        if (tid < 256 && s + 2 < T_)
            xfut = xpd[((size_t)(t + 2*step) * B_ + b) * H_ + j];  // 2-deep prefetch

        float2 acc2 = make_float2(0.f, 0.f);
#pragma unroll
        for (int q = 0; q < WREG2/2; q++) {            // 24 float4 of h
            float4 hv = h4p[q];
            ffma2(acc2, make_float2(hv.x, hv.y), wreg2[2*q]);
            ffma2(acc2, make_float2(hv.z, hv.w), wreg2[2*q+1]);
        }
#pragma unroll
        for (int q = 0; q < WSH2/2; q++) {             // 8 float4 of h
            float4 hv = h4p[WREG2/2 + q];
            float2 w0 = Wt2[(2*q  )*512 + tid];
            float2 w1 = Wt2[(2*q+1)*512 + tid];
            ffma2(acc2, make_float2(hv.x, hv.y), w0);
            ffma2(acc2, make_float2(hv.z, hv.w), w1);
        }
        partial[tid] = acc2.x + acc2.y;
        __syncthreads();
        if (tid < 256) {
            float a = partial[tid] + partial[tid + 256] + xv;
            float hn = tanhf(a);
            hsh[tid] = hn;                 // safe: all reads of old h done pre-barrier
            outp[(size_t)t * 512] = hn;
        }
        __syncthreads();
        xv = xnv; xnv = xfut;
        t += step;
    }
}

// ---------------- 4) head projections: relu(x2) @ [13x512]^T + biases ----------------
__global__ __launch_bounds__(256) void head_xp_kernel(
    const float* __restrict__ wi, const float* __restrict__ bi_ih, const float* __restrict__ bi_hh,
    const float* __restrict__ wf, const float* __restrict__ bf_ih, const float* __restrict__ bf_hh,
    const float* __restrict__ wc, const float* __restrict__ bc_ih, const float* __restrict__ bc_hh)
{
    __shared__ float Ws[13 * 512];
    __shared__ float bs[13];
    int tid = threadIdx.x;
    for (int idx = tid; idx < 13 * 512; idx += 256) {
        int n = idx / 512, k = idx % 512;
        float w;
        if (n < 3)      w = wi[n*512 + k];
        else if (n < 8) w = wf[(n-3)*512 + k];
        else            w = wc[(n-8)*512 + k];
        Ws[idx] = w;
    }
    if (tid < 13) {
        float bv;
        if (tid < 3)      bv = bi_ih[tid]   + bi_hh[tid];
        else if (tid < 8) bv = bf_ih[tid-3] + bf_hh[tid-3];
        else              bv = bc_ih[tid-8] + bc_hh[tid-8];
        bs[tid] = bv;
    }
    __syncthreads();

    int w = tid >> 5, lane = tid & 31;
    int m = blockIdx.x * 8 + w;
    const float* xr = g_x2 + (size_t)m * 512;

    float acc[13];
#pragma unroll
    for (int n = 0; n < 13; n++) acc[n] = 0.f;

    for (int i = 0; i < 16; i++) {
        int k = i * 32 + lane;
        float xv = xr[k];
        xv = xv > 0.f ? xv : 0.f;
#pragma unroll
        for (int n = 0; n < 13; n++) acc[n] += xv * Ws[n*512 + k];
    }
#pragma unroll
    for (int n = 0; n < 13; n++) {
#pragma unroll
        for (int off = 16; off; off >>= 1)
            acc[n] += __shfl_xor_sync(0xffffffff, acc[n], off);
    }
    if (lane == 0) {
        int bb = m >> 10, t = m & 1023;
        float* o = g_xph + ((size_t)t * B_ + bb) * 16;
#pragma unroll
        for (int n = 0; n < 13; n++) o[n] = acc[n] + bs[n];
    }
}

// ---------------- 5) head recurrences (3 tiny forward scans) ----------------
__global__ void head_rnn_kernel(
    const float* __restrict__ wi_hh,
    const float* __restrict__ wf_hh,
    const float* __restrict__ wc_hh,
    float* __restrict__ out)
{
    int hid = blockIdx.x % 3;
    int b   = blockIdx.x / 3;
    int lane = threadIdx.x;
    int C, off;
    size_t outoff;
    const float* Whh;
    if (hid == 0)      { C = 3; off = 0; outoff = 0;                         Whh = wi_hh; }
    else if (hid == 1) { C = 5; off = 3; outoff = (size_t)B_*T_*3;           Whh = wf_hh; }
    else               { C = 5; off = 8; outoff = (size_t)B_*T_*3 + (size_t)B_*T_*5; Whh = wc_hh; }

    float w[5] = {0,0,0,0,0};
    if (lane < C)
        for (int k = 0; k < C; k++) w[k] = Whh[lane*C + k];

    float h = 0.f;
    float* ob = out + outoff + (size_t)b * T_ * C;
    for (int t = 0; t < T_; t++) {
        float xv = (lane < C) ? g_xph[((size_t)t * B_ + b) * 16 + off + lane] : 0.f;
        float h0 = __shfl_sync(0xffffffff, h, 0);
        float h1 = __shfl_sync(0xffffffff, h, 1);
        float h2 = __shfl_sync(0xffffffff, h, 2);
        float h3 = __shfl_sync(0xffffffff, h, 3);
        float h4 = __shfl_sync(0xffffffff, h, 4);
        float acc = xv + h0*w[0] + h1*w[1] + h2*w[2] + h3*w[3] + h4*w[4];
        h = tanhf(acc);
        if (lane < C) ob[(size_t)t * C + lane] = h;
    }
}

// ---------------- launch ----------------
extern "C" void kernel_launch(void* const* d_in, const int* in_sizes, int n_in,
                              void* d_out, int out_size) {
    const int*   tokens = (const int*)  d_in[0];
    const float* emb    = (const float*)d_in[1];
    const float* w_ih   = (const float*)d_in[2];   // [2][2][256][512]
    const float* w_hh   = (const float*)d_in[3];   // [2][2][256][256]
    const float* b_ih   = (const float*)d_in[4];   // [2][2][256]
    const float* b_hh   = (const float*)d_in[5];
    const float* iw_ih  = (const float*)d_in[6];
    const float* iw_hh  = (const float*)d_in[7];
    const float* ib_ih  = (const float*)d_in[8];
    const float* ib_hh  = (const float*)d_in[9];
    const float* fw_ih  = (const float*)d_in[10];
    const float* fw_hh  = (const float*)d_in[11];
    const float* fb_ih  = (const float*)d_in[12];
    const float* fb_hh  = (const float*)d_in[13];
    const float* cw_ih  = (const float*)d_in[14];
    const float* cw_hh  = (const float*)d_in[15];
    const float* cb_ih  = (const float*)d_in[16];
    const float* cb_hh  = (const float*)d_in[17];
    float* out = (float*)d_out;

    const int rnn_smem = (WSH2 * 512 * 2 + 256 + 512) * 4;   // ~68.6 KB
    cudaFuncSetAttribute(rnn_layer_kernel,
                         cudaFuncAttributeMaxDynamicSharedMemorySize, rnn_smem);

    // 1) gather embeddings
    embed_kernel<<<(M_ * (E_/4)) / 256, 256>>>(tokens, emb);

    // 2) layer 0: projection + scan
    gemm_xp_kernel<<<dim3(M_/128, 512/128), 256>>>(0, w_ih, b_ih, b_hh);
    rnn_layer_kernel<<<B_ * 2, 512, rnn_smem>>>(w_hh, 0);

    // 3) layer 1: projection + scan
    gemm_xp_kernel<<<dim3(M_/128, 512/128), 256>>>(1, w_ih + 2*H_*E_,
                                                   b_ih + 2*H_, b_hh + 2*H_);
    rnn_layer_kernel<<<B_ * 2, 512, rnn_smem>>>(w_hh + 2*H_*H_, 1);

    // 4) head projections (with ReLU on the fly)
    head_xp_kernel<<<M_/8, 256>>>(iw_ih, ib_ih, ib_hh,
                                  fw_ih, fb_ih, fb_hh,
                                  cw_ih, cb_ih, cb_hh);

    // 5) head scans -> final output
    head_rnn_kernel<<<B_ * 3, 32>>>(iw_hh, fw_hh, cw_hh, out);
}

// round 5
// speedup vs baseline: 1.1727x; 1.0181x over previous
#include <cuda_runtime.h>
#include <math.h>

#define B_ 64
#define T_ 1024
#define E_ 512
#define H_ 256
#define M_ (B_*T_)          // 65536

// RNN: 512 threads, thread pair (2j, 2j+1) computes channel j.
// Each thread covers 128 of the 256 h-elements: 96 in registers + 32 in smem.
#define WREG2 48            // float2 weights in registers per thread
#define WSH2  16            // float2 weights in shared per thread
#define HSTRIDE 132         // padded half-stride (132 % 32 == 4 -> bank shift)
#define HBUF   264          // one h buffer (2 halves)

// ---------------- scratch (device globals; no allocation allowed) ----------------
__device__ float g_x0[(size_t)M_*E_];          // embedded input        [M,512]
__device__ float g_xp[(size_t)2*T_*B_*H_];     // per-layer projections [2][T][B][H]
__device__ float g_x1[(size_t)M_*512];         // layer0 output concat  [M,512]
__device__ float g_x2[(size_t)M_*512];         // layer1 output concat  [M,512]
__device__ float g_xph[(size_t)T_*B_*16];      // head projections      [T][B][16] (13 used)

// ---------------- packed f32x2 FMA (Blackwell) ----------------
__device__ __forceinline__ void ffma2(float2 &acc, float2 a, float2 b) {
    asm("fma.rn.f32x2 %0, %1, %2, %0;"
        : "+l"(reinterpret_cast<unsigned long long&>(acc))
        : "l"(reinterpret_cast<unsigned long long&>(a)),
          "l"(reinterpret_cast<unsigned long long&>(b)));
}

// fast tanh: exp2-based, ~1e-6 relative error
__device__ __forceinline__ float ftanh(float x) {
    float ax = fabsf(x);
    float e  = __expf(-2.f * ax);
    float r  = __fdividef(1.f - e, 1.f + e);
    return copysignf(r, x);
}

// ---------------- 1) embedding gather ----------------
__global__ void embed_kernel(const int* __restrict__ tokens,
                             const float* __restrict__ emb) {
    int idx = blockIdx.x * 256 + threadIdx.x;   // float4 index, total M_*128
    int m   = idx >> 7;
    int e4  = idx & 127;
    int tok = __ldg(&tokens[m]);
    reinterpret_cast<float4*>(g_x0)[idx] =
        reinterpret_cast<const float4*>(emb + (size_t)tok * E_)[e4];
}

// ---------------- 2) input projection GEMM (double-buffered smem) ----------------
// C[m,n] = sum_k A[m,k] * W[n,k] + bih[n] + bhh[n], written to
// g_xp[d][t][b][h] with d=n>>8, h=n&255, b=m>>10, t=m&1023.
__global__ __launch_bounds__(256, 2) void gemm_xp_kernel(
    int which_A,                       // 0: g_x0, 1: g_x1
    const float* __restrict__ W,       // [512,512]
    const float* __restrict__ bih,     // [512]
    const float* __restrict__ bhh)     // [512]
{
    __shared__ float As[2][8][128];
    __shared__ float Bs[2][8][128];
    const float* A = which_A ? g_x1 : g_x0;

    int tid = threadIdx.x;
    int m0 = blockIdx.x * 128;
    int n0 = blockIdx.y * 128;
    int lr = tid >> 1, lh = tid & 1;
    const float* Ap = A + (size_t)(m0 + lr) * 512 + lh * 4;
    const float* Wp = W + (size_t)(n0 + lr) * 512 + lh * 4;
    int ty = tid >> 4, tx = tid & 15;

    float2 acc[8][4];
#pragma unroll
    for (int i = 0; i < 8; i++)
#pragma unroll
        for (int j = 0; j < 4; j++) acc[i][j] = make_float2(0.f, 0.f);

    // preload tile 0
    {
        float4 av = *(const float4*)Ap;
        float4 wv = *(const float4*)Wp;
        As[0][lh*4+0][lr] = av.x; As[0][lh*4+1][lr] = av.y;
        As[0][lh*4+2][lr] = av.z; As[0][lh*4+3][lr] = av.w;
        Bs[0][lh*4+0][lr] = wv.x; Bs[0][lh*4+1][lr] = wv.y;
        Bs[0][lh*4+2][lr] = wv.z; Bs[0][lh*4+3][lr] = wv.w;
    }
    __syncthreads();

    for (int k0 = 0; k0 < 512; k0 += 8) {
        int p = (k0 >> 3) & 1;
        float4 av, wv;
        bool more = (k0 + 8 < 512);
        if (more) {                                 // prefetch next tile -> regs
            av = *(const float4*)(Ap + k0 + 8);
            wv = *(const float4*)(Wp + k0 + 8);
        }
#pragma unroll
        for (int kk = 0; kk < 8; kk++) {
            float a[8];
            *(float4*)&a[0] = *(const float4*)&As[p][kk][ty*8];
            *(float4*)&a[4] = *(const float4*)&As[p][kk][ty*8+4];
            float4 b0 = *(const float4*)&Bs[p][kk][tx*8];
            float4 b1 = *(const float4*)&Bs[p][kk][tx*8+4];
            float2 bp[4] = { make_float2(b0.x,b0.y), make_float2(b0.z,b0.w),
                             make_float2(b1.x,b1.y), make_float2(b1.z,b1.w) };
#pragma unroll
            for (int i = 0; i < 8; i++) {
                float2 ap = make_float2(a[i], a[i]);
#pragma unroll
                for (int j = 0; j < 4; j++) ffma2(acc[i][j], ap, bp[j]);
            }
        }
        if (more) {                                 // store into other buffer
            int q = p ^ 1;
            As[q][lh*4+0][lr] = av.x; As[q][lh*4+1][lr] = av.y;
            As[q][lh*4+2][lr] = av.z; As[q][lh*4+3][lr] = av.w;
            Bs[q][lh*4+0][lr] = wv.x; Bs[q][lh*4+1][lr] = wv.y;
            Bs[q][lh*4+2][lr] = wv.z; Bs[q][lh*4+3][lr] = wv.w;
        }
        __syncthreads();
    }

#pragma unroll
    for (int i = 0; i < 8; i++) {
        int m = m0 + ty*8 + i;
        int bb = m >> 10, t = m & 1023;
#pragma unroll
        for (int p = 0; p < 2; p++) {
            int n = n0 + tx*8 + p*4;
            int d = n >> 8, h = n & 255;
            float4 v;
            v.x = acc[i][p*2  ].x + bih[n  ] + bhh[n  ];
            v.y = acc[i][p*2  ].y + bih[n+1] + bhh[n+1];
            v.z = acc[i][p*2+1].x + bih[n+2] + bhh[n+2];
            v.w = acc[i][p*2+1].y + bih[n+3] + bhh[n+3];
            *(float4*)&g_xp[(((size_t)d*T_ + t)*B_ + bb)*H_ + h] = v;
        }
    }
}

// ---------------- 3) bidirectional RNN recurrence ----------------
// One CTA per (batch, dir). 512 threads. Thread tid: channel j=tid>>1,
// half=tid&1 covering h[half*128 : half*128+128). Partner reduce via shfl.
// Double-buffered h -> ONE barrier per step.
__global__ __launch_bounds__(512, 1) void rnn_layer_kernel(
    const float* __restrict__ whh,     // [2][H][H] (this layer)
    int which_out)                     // 0 -> g_x1, 1 -> g_x2
{
    extern __shared__ float sm[];
    float2* Wt2  = (float2*)sm;                  // [WSH2][512] float2
    float*  hbuf = sm + WSH2 * 512 * 2;          // [2][HBUF]
    float*  xnext = which_out ? g_x2 : g_x1;

    int tid  = threadIdx.x;
    int j    = tid >> 1;          // output channel
    int half = tid & 1;           // which 128-slice of h
    int d = blockIdx.x & 1;
    int b = blockIdx.x >> 1;
    const float* Wd = whh + (size_t)d * H_ * H_;

    // register weights: W[j][half*128 + 2k], k=0..47
    float2 wreg2[WREG2];
    {
        const float2* wrow = (const float2*)(Wd + (size_t)j * H_ + half * 128);
#pragma unroll
        for (int k = 0; k < WREG2; k++) wreg2[k] = wrow[k];
    }
    // shared weights, transposed: Wt2[kk*512+tid] = W[j][half*128+96+2kk..+1]
    for (int idx = tid; idx < WSH2 * 512; idx += 512) {
        int kk = idx >> 9;
        int t2 = idx & 511;
        int j2 = t2 >> 1, h2 = t2 & 1;
        Wt2[idx] = *(const float2*)(Wd + (size_t)j2 * H_ + h2 * 128 + 2*WREG2 + 2*kk);
    }
    for (int idx = tid; idx < 2 * HBUF; idx += 512) hbuf[idx] = 0.f;
    __syncthreads();

    const float* xpd = g_xp + (size_t)d * T_ * B_ * H_;
    float* outp = xnext + (size_t)b * T_ * 512 + d * H_ + j;

    int t = d ? (T_ - 1) : 0;
    int step = d ? -1 : 1;

    float xv  = xpd[((size_t)t * B_ + b) * H_ + j];
    float xnv = xpd[((size_t)(t + step) * B_ + b) * H_ + j];

    int rb = 0;
    for (int s = 0; s < T_; ++s) {
        float xfut = 0.f;
        if (s + 2 < T_)
            xfut = xpd[((size_t)(t + 2*step) * B_ + b) * H_ + j];  // 2-deep prefetch

        const float4* h4p = (const float4*)(hbuf + rb * HBUF + half * HSTRIDE);

        float2 a0 = make_float2(0.f,0.f), a1 = a0, a2 = a0, a3 = a0;
#pragma unroll
        for (int q = 0; q < WREG2/2; q++) {            // 24 float4 of h (regs)
            float4 hv = h4p[q];
            ffma2((q & 1) ? a2 : a0, make_float2(hv.x, hv.y), wreg2[2*q]);
            ffma2((q & 1) ? a3 : a1, make_float2(hv.z, hv.w), wreg2[2*q+1]);
        }
#pragma unroll
        for (int q = 0; q < WSH2/2; q++) {             // 8 float4 of h (smem W)
            float4 hv = h4p[WREG2/2 + q];
            float2 w0 = Wt2[(2*q  )*512 + tid];
            float2 w1 = Wt2[(2*q+1)*512 + tid];
            ffma2((q & 1) ? a2 : a0, make_float2(hv.x, hv.y), w0);
            ffma2((q & 1) ? a3 : a1, make_float2(hv.z, hv.w), w1);
        }
        float ssum = (a0.x + a0.y) + (a1.x + a1.y)
                   + (a2.x + a2.y) + (a3.x + a3.y);
        float psum = __shfl_xor_sync(0xffffffffu, ssum, 1);
        float hn = ftanh(ssum + psum + xv);

        int wb = rb ^ 1;
        if (half == 0) hbuf[wb * HBUF + j + ((j >> 7) << 2)] = hn;  // padded pos
        else           outp[(size_t)t * 512] = hn;

        __syncthreads();                 // new h visible; old h reads all done
        xv = xnv; xnv = xfut;
        t += step;
        rb = wb;
    }
}

// ---------------- 4) head projections: relu(x2) @ [13x512]^T + biases ----------------
__global__ __launch_bounds__(256) void head_xp_kernel(
    const float* __restrict__ wi, const float* __restrict__ bi_ih, const float* __restrict__ bi_hh,
    const float* __restrict__ wf, const float* __restrict__ bf_ih, const float* __restrict__ bf_hh,
    const float* __restrict__ wc, const float* __restrict__ bc_ih, const float* __restrict__ bc_hh)
{
    __shared__ float Ws[13 * 512];
    __shared__ float bs[13];
    int tid = threadIdx.x;
    for (int idx = tid; idx < 13 * 512; idx += 256) {
        int n = idx / 512, k = idx % 512;
        float w;
        if (n < 3)      w = wi[n*512 + k];
        else if (n < 8) w = wf[(n-3)*512 + k];
        else            w = wc[(n-8)*512 + k];
        Ws[idx] = w;
    }
    if (tid < 13) {
        float bv;
        if (tid < 3)      bv = bi_ih[tid]   + bi_hh[tid];
        else if (tid < 8) bv = bf_ih[tid-3] + bf_hh[tid-3];
        else              bv = bc_ih[tid-8] + bc_hh[tid-8];
        bs[tid] = bv;
    }
    __syncthreads();

    int w = tid >> 5, lane = tid & 31;
    int m = blockIdx.x * 8 + w;
    const float* xr = g_x2 + (size_t)m * 512;

    float acc[13];
#pragma unroll
    for (int n = 0; n < 13; n++) acc[n] = 0.f;

    for (int i = 0; i < 16; i++) {
        int k = i * 32 + lane;
        float xv = xr[k];
        xv = xv > 0.f ? xv : 0.f;
#pragma unroll
        for (int n = 0; n < 13; n++) acc[n] += xv * Ws[n*512 + k];
    }
#pragma unroll
    for (int n = 0; n < 13; n++) {
#pragma unroll
        for (int off = 16; off; off >>= 1)
            acc[n] += __shfl_xor_sync(0xffffffff, acc[n], off);
    }
    if (lane == 0) {
        int bb = m >> 10, t = m & 1023;
        float* o = g_xph + ((size_t)t * B_ + bb) * 16;
#pragma unroll
        for (int n = 0; n < 13; n++) o[n] = acc[n] + bs[n];
    }
}

// ---------------- 5) head recurrences (3 tiny forward scans) ----------------
__global__ void head_rnn_kernel(
    const float* __restrict__ wi_hh,
    const float* __restrict__ wf_hh,
    const float* __restrict__ wc_hh,
    float* __restrict__ out)
{
    int hid = blockIdx.x % 3;
    int b   = blockIdx.x / 3;
    int lane = threadIdx.x;
    int C, off;
    size_t outoff;
    const float* Whh;
    if (hid == 0)      { C = 3; off = 0; outoff = 0;                         Whh = wi_hh; }
    else if (hid == 1) { C = 5; off = 3; outoff = (size_t)B_*T_*3;           Whh = wf_hh; }
    else               { C = 5; off = 8; outoff = (size_t)B_*T_*3 + (size_t)B_*T_*5; Whh = wc_hh; }

    float w[5] = {0,0,0,0,0};
    if (lane < C)
        for (int k = 0; k < C; k++) w[k] = Whh[lane*C + k];

    float h = 0.f;
    float* ob = out + outoff + (size_t)b * T_ * C;
    for (int t = 0; t < T_; t++) {
        float xv = (lane < C) ? g_xph[((size_t)t * B_ + b) * 16 + off + lane] : 0.f;
        float h0 = __shfl_sync(0xffffffff, h, 0);
        float h1 = __shfl_sync(0xffffffff, h, 1);
        float h2 = __shfl_sync(0xffffffff, h, 2);
        float h3 = __shfl_sync(0xffffffff, h, 3);
        float h4 = __shfl_sync(0xffffffff, h, 4);
        float acc = xv + h0*w[0] + h1*w[1] + h2*w[2] + h3*w[3] + h4*w[4];
        h = ftanh(acc);
        if (lane < C) ob[(size_t)t * C + lane] = h;
    }
}

// ---------------- launch ----------------
extern "C" void kernel_launch(void* const* d_in, const int* in_sizes, int n_in,
                              void* d_out, int out_size) {
    const int*   tokens = (const int*)  d_in[0];
    const float* emb    = (const float*)d_in[1];
    const float* w_ih   = (const float*)d_in[2];   // [2][2][256][512]
    const float* w_hh   = (const float*)d_in[3];   // [2][2][256][256]
    const float* b_ih   = (const float*)d_in[4];   // [2][2][256]
    const float* b_hh   = (const float*)d_in[5];
    const float* iw_ih  = (const float*)d_in[6];
    const float* iw_hh  = (const float*)d_in[7];
    const float* ib_ih  = (const float*)d_in[8];
    const float* ib_hh  = (const float*)d_in[9];
    const float* fw_ih  = (const float*)d_in[10];
    const float* fw_hh  = (const float*)d_in[11];
    const float* fb_ih  = (const float*)d_in[12];
    const float* fb_hh  = (const float*)d_in[13];
    const float* cw_ih  = (const float*)d_in[14];
    const float* cw_hh  = (const float*)d_in[15];
    const float* cb_ih  = (const float*)d_in[16];
    const float* cb_hh  = (const float*)d_in[17];
    float* out = (float*)d_out;

    const int rnn_smem = (WSH2 * 512 * 2 + 2 * HBUF) * 4;   // ~67.7 KB
    cudaFuncSetAttribute(rnn_layer_kernel,
                         cudaFuncAttributeMaxDynamicSharedMemorySize, rnn_smem);

    // 1) gather embeddings
    embed_kernel<<<(M_ * (E_/4)) / 256, 256>>>(tokens, emb);

    // 2) layer 0: projection + scan
    gemm_xp_kernel<<<dim3(M_/128, 512/128), 256>>>(0, w_ih, b_ih, b_hh);
    rnn_layer_kernel<<<B_ * 2, 512, rnn_smem>>>(w_hh, 0);

    // 3) layer 1: projection + scan
    gemm_xp_kernel<<<dim3(M_/128, 512/128), 256>>>(1, w_ih + 2*H_*E_,
                                                   b_ih + 2*H_, b_hh + 2*H_);
    rnn_layer_kernel<<<B_ * 2, 512, rnn_smem>>>(w_hh + 2*H_*H_, 1);

    // 4) head projections (with ReLU on the fly)
    head_xp_kernel<<<M_/8, 256>>>(iw_ih, ib_ih, ib_hh,
                                  fw_ih, fb_ih, fb_hh,
                                  cw_ih, cb_ih, cb_hh);

    // 5) head scans -> final output
    head_rnn_kernel<<<B_ * 3, 32>>>(iw_hh, fw_hh, cw_hh, out);
}

// round 6
// speedup vs baseline: 1.2143x; 1.0355x over previous
#include <cuda_runtime.h>
#include <math.h>

#define B_ 64
#define T_ 1024
#define E_ 512
#define H_ 256
#define M_ (B_*T_)          // 65536

// RNN: 512 threads, thread pair (2j, 2j+1) computes channel j.
// Each thread covers 128 of the 256 h-elements: 96 in registers + 32 in smem.
#define WREG2 48            // float2 weights in registers per thread
#define WSH4  8             // float4 weights in shared per thread
#define HSTRIDE 132         // padded half-stride (132 % 32 == 4 -> bank shift)
#define HBUF   264          // one h buffer (2 halves)

// ---------------- scratch (device globals; no allocation allowed) ----------------
__device__ float g_xp[(size_t)2*T_*B_*H_];     // per-layer projections [2][T][B][H]
__device__ float g_x1[(size_t)M_*512];         // layer0 output concat  [M,512]
__device__ float g_x2[(size_t)M_*512];         // layer1 output concat  [M,512]
__device__ float g_xph[(size_t)T_*B_*16];      // head projections      [T][B][16] (13 used)

// ---------------- packed f32x2 FMA (Blackwell) ----------------
__device__ __forceinline__ void ffma2(float2 &acc, float2 a, float2 b) {
    asm("fma.rn.f32x2 %0, %1, %2, %0;"
        : "+l"(reinterpret_cast<unsigned long long&>(acc))
        : "l"(reinterpret_cast<unsigned long long&>(a)),
          "l"(reinterpret_cast<unsigned long long&>(b)));
}

// fast tanh: exp-based, ~1e-6 relative error
__device__ __forceinline__ float ftanh(float x) {
    float ax = fabsf(x);
    float e  = __expf(-2.f * ax);
    float r  = __fdividef(1.f - e, 1.f + e);
    return copysignf(r, x);
}

// ---------------- 1) input projection GEMM (k-tile 16, double-buffered) -------
// A row m: which_A==0 -> emb[tokens[m]] (fused gather), else g_x1 row m.
// C[m,n] = sum_k A[m,k]*W[n,k] + bih[n] + bhh[n]  -> g_xp[d][t][b][h]
__global__ __launch_bounds__(256, 2) void gemm_xp_kernel(
    int which_A,
    const int*   __restrict__ tokens,  // [M]
    const float* __restrict__ emb,     // [V,512]
    const float* __restrict__ W,       // [512,512]
    const float* __restrict__ bih,     // [512]
    const float* __restrict__ bhh)     // [512]
{
    __shared__ float As[2][16][128];
    __shared__ float Bs[2][16][128];

    int tid = threadIdx.x;
    int m0 = blockIdx.x * 128;
    int n0 = blockIdx.y * 128;
    int lr = tid >> 1, lh = tid & 1;          // row 0..127, col-half 0/1

    const float* Ap;
    if (which_A) {
        Ap = g_x1 + (size_t)(m0 + lr) * 512 + lh * 8;
    } else {
        int tok = __ldg(&tokens[m0 + lr]);
        Ap = emb + (size_t)tok * 512 + lh * 8;
    }
    const float* Wp = W + (size_t)(n0 + lr) * 512 + lh * 8;
    int ty = tid >> 4, tx = tid & 15;

    float2 acc[8][4];
#pragma unroll
    for (int i = 0; i < 8; i++)
#pragma unroll
        for (int j = 0; j < 4; j++) acc[i][j] = make_float2(0.f, 0.f);

    // preload tile 0
    {
        float4 a0 = *(const float4*)(Ap);
        float4 a1 = *(const float4*)(Ap + 4);
        float4 w0 = *(const float4*)(Wp);
        float4 w1 = *(const float4*)(Wp + 4);
        As[0][lh*8+0][lr]=a0.x; As[0][lh*8+1][lr]=a0.y; As[0][lh*8+2][lr]=a0.z; As[0][lh*8+3][lr]=a0.w;
        As[0][lh*8+4][lr]=a1.x; As[0][lh*8+5][lr]=a1.y; As[0][lh*8+6][lr]=a1.z; As[0][lh*8+7][lr]=a1.w;
        Bs[0][lh*8+0][lr]=w0.x; Bs[0][lh*8+1][lr]=w0.y; Bs[0][lh*8+2][lr]=w0.z; Bs[0][lh*8+3][lr]=w0.w;
        Bs[0][lh*8+4][lr]=w1.x; Bs[0][lh*8+5][lr]=w1.y; Bs[0][lh*8+6][lr]=w1.z; Bs[0][lh*8+7][lr]=w1.w;
    }
    __syncthreads();

    for (int k0 = 0; k0 < 512; k0 += 16) {
        int p = (k0 >> 4) & 1;
        float4 a0, a1, w0, w1;
        bool more = (k0 + 16 < 512);
        if (more) {
            a0 = *(const float4*)(Ap + k0 + 16);
            a1 = *(const float4*)(Ap + k0 + 20);
            w0 = *(const float4*)(Wp + k0 + 16);
            w1 = *(const float4*)(Wp + k0 + 20);
        }
#pragma unroll
        for (int kk = 0; kk < 16; kk++) {
            float a[8];
            *(float4*)&a[0] = *(const float4*)&As[p][kk][ty*8];
            *(float4*)&a[4] = *(const float4*)&As[p][kk][ty*8+4];
            float4 b0 = *(const float4*)&Bs[p][kk][tx*8];
            float4 b1 = *(const float4*)&Bs[p][kk][tx*8+4];
            float2 bp[4] = { make_float2(b0.x,b0.y), make_float2(b0.z,b0.w),
                             make_float2(b1.x,b1.y), make_float2(b1.z,b1.w) };
#pragma unroll
            for (int i = 0; i < 8; i++) {
                float2 ap = make_float2(a[i], a[i]);
#pragma unroll
                for (int j = 0; j < 4; j++) ffma2(acc[i][j], ap, bp[j]);
            }
        }
        if (more) {
            int q = p ^ 1;
            As[q][lh*8+0][lr]=a0.x; As[q][lh*8+1][lr]=a0.y; As[q][lh*8+2][lr]=a0.z; As[q][lh*8+3][lr]=a0.w;
            As[q][lh*8+4][lr]=a1.x; As[q][lh*8+5][lr]=a1.y; As[q][lh*8+6][lr]=a1.z; As[q][lh*8+7][lr]=a1.w;
            Bs[q][lh*8+0][lr]=w0.x; Bs[q][lh*8+1][lr]=w0.y; Bs[q][lh*8+2][lr]=w0.z; Bs[q][lh*8+3][lr]=w0.w;
            Bs[q][lh*8+4][lr]=w1.x; Bs[q][lh*8+5][lr]=w1.y; Bs[q][lh*8+6][lr]=w1.z; Bs[q][lh*8+7][lr]=w1.w;
        }
        __syncthreads();
    }

#pragma unroll
    for (int i = 0; i < 8; i++) {
        int m = m0 + ty*8 + i;
        int bb = m >> 10, t = m & 1023;
#pragma unroll
        for (int p = 0; p < 2; p++) {
            int n = n0 + tx*8 + p*4;
            int d = n >> 8, h = n & 255;
            float4 v;
            v.x = acc[i][p*2  ].x + bih[n  ] + bhh[n  ];
            v.y = acc[i][p*2  ].y + bih[n+1] + bhh[n+1];
            v.z = acc[i][p*2+1].x + bih[n+2] + bhh[n+2];
            v.w = acc[i][p*2+1].y + bih[n+3] + bhh[n+3];
            *(float4*)&g_xp[(((size_t)d*T_ + t)*B_ + bb)*H_ + h] = v;
        }
    }
}

// ---------------- 2) bidirectional RNN recurrence ----------------
// One CTA per (batch, dir). 512 threads. Thread tid: channel j=tid>>1,
// half=tid&1 covering h[half*128 : half*128+128). Partner reduce via shfl.
// Double-buffered h -> ONE barrier per step. smem weights as float4.
__global__ __launch_bounds__(512, 1) void rnn_layer_kernel(
    const float* __restrict__ whh,     // [2][H][H] (this layer)
    int which_out)                     // 0 -> g_x1, 1 -> g_x2
{
    extern __shared__ float sm[];
    float4* Wt4  = (float4*)sm;                  // [WSH4][512] float4
    float*  hbuf = sm + WSH4 * 512 * 4;          // [2][HBUF]
    float*  xnext = which_out ? g_x2 : g_x1;

    int tid  = threadIdx.x;
    int j    = tid >> 1;          // output channel
    int half = tid & 1;           // which 128-slice of h
    int d = blockIdx.x & 1;
    int b = blockIdx.x >> 1;
    const float* Wd = whh + (size_t)d * H_ * H_;

    // register weights: W[j][half*128 + 2k], k=0..47
    float2 wreg2[WREG2];
    {
        const float2* wrow = (const float2*)(Wd + (size_t)j * H_ + half * 128);
#pragma unroll
        for (int k = 0; k < WREG2; k++) wreg2[k] = wrow[k];
    }
    // shared weights: Wt4[kk*512+tid] = W[j][half*128 + 96 + 4kk .. +3]
    for (int idx = tid; idx < WSH4 * 512; idx += 512) {
        int kk = idx >> 9;
        int t2 = idx & 511;
        int j2 = t2 >> 1, h2 = t2 & 1;
        Wt4[idx] = *(const float4*)(Wd + (size_t)j2 * H_ + h2 * 128 + 2*WREG2 + 4*kk);
    }
    for (int idx = tid; idx < 2 * HBUF; idx += 512) hbuf[idx] = 0.f;
    __syncthreads();

    const float* xpd = g_xp + (size_t)d * T_ * B_ * H_;
    float* outp = xnext + (size_t)b * T_ * 512 + d * H_ + j;

    int t = d ? (T_ - 1) : 0;
    int step = d ? -1 : 1;

    float xv  = xpd[((size_t)t * B_ + b) * H_ + j];
    float xnv = xpd[((size_t)(t + step) * B_ + b) * H_ + j];

    int rb = 0;
    for (int s = 0; s < T_; ++s) {
        float xfut = 0.f;
        if (s + 2 < T_)
            xfut = xpd[((size_t)(t + 2*step) * B_ + b) * H_ + j];  // 2-deep prefetch

        const float4* h4p = (const float4*)(hbuf + rb * HBUF + half * HSTRIDE);

        float2 a0 = make_float2(0.f,0.f), a1 = a0, a2 = a0, a3 = a0;
#pragma unroll
        for (int q = 0; q < WREG2/2; q++) {            // 24 float4 of h (reg W)
            float4 hv = h4p[q];
            ffma2((q & 1) ? a2 : a0, make_float2(hv.x, hv.y), wreg2[2*q]);
            ffma2((q & 1) ? a3 : a1, make_float2(hv.z, hv.w), wreg2[2*q+1]);
        }
#pragma unroll
        for (int q = 0; q < WSH4; q++) {               // 8 float4 of h (smem W)
            float4 hv = h4p[WREG2/2 + q];
            float4 w  = Wt4[q*512 + tid];
            ffma2((q & 1) ? a2 : a0, make_float2(hv.x, hv.y), make_float2(w.x, w.y));
            ffma2((q & 1) ? a3 : a1, make_float2(hv.z, hv.w), make_float2(w.z, w.w));
        }
        float ssum = (a0.x + a0.y) + (a1.x + a1.y)
                   + (a2.x + a2.y) + (a3.x + a3.y);
        float psum = __shfl_xor_sync(0xffffffffu, ssum, 1);
        float hn = ftanh(ssum + psum + xv);

        int wb = rb ^ 1;
        if (half == 0) hbuf[wb * HBUF + j + ((j >> 7) << 2)] = hn;  // padded pos
        else           outp[(size_t)t * 512] = hn;

        __syncthreads();                 // new h visible; old h reads all done
        xv = xnv; xnv = xfut;
        t += step;
        rb = wb;
    }
}

// ---------------- 3) head projections: relu(x2) @ [13x512]^T + biases ----------------
__global__ __launch_bounds__(256) void head_xp_kernel(
    const float* __restrict__ wi, const float* __restrict__ bi_ih, const float* __restrict__ bi_hh,
    const float* __restrict__ wf, const float* __restrict__ bf_ih, const float* __restrict__ bf_hh,
    const float* __restrict__ wc, const float* __restrict__ bc_ih, const float* __restrict__ bc_hh)
{
    __shared__ float Ws[13 * 512];
    __shared__ float bs[13];
    int tid = threadIdx.x;
    for (int idx = tid; idx < 13 * 512; idx += 256) {
        int n = idx / 512, k = idx % 512;
        float w;
        if (n < 3)      w = wi[n*512 + k];
        else if (n < 8) w = wf[(n-3)*512 + k];
        else            w = wc[(n-8)*512 + k];
        Ws[idx] = w;
    }
    if (tid < 13) {
        float bv;
        if (tid < 3)      bv = bi_ih[tid]   + bi_hh[tid];
        else if (tid < 8) bv = bf_ih[tid-3] + bf_hh[tid-3];
        else              bv = bc_ih[tid-8] + bc_hh[tid-8];
        bs[tid] = bv;
    }
    __syncthreads();

    int w = tid >> 5, lane = tid & 31;
    int m = blockIdx.x * 8 + w;
    const float* xr = g_x2 + (size_t)m * 512;

    float acc[13];
#pragma unroll
    for (int n = 0; n < 13; n++) acc[n] = 0.f;

    for (int i = 0; i < 16; i++) {
        int k = i * 32 + lane;
        float xv = xr[k];
        xv = xv > 0.f ? xv : 0.f;
#pragma unroll
        for (int n = 0; n < 13; n++) acc[n] += xv * Ws[n*512 + k];
    }
#pragma unroll
    for (int n = 0; n < 13; n++) {
#pragma unroll
        for (int off = 16; off; off >>= 1)
            acc[n] += __shfl_xor_sync(0xffffffff, acc[n], off);
    }
    if (lane == 0) {
        int bb = m >> 10, t = m & 1023;
        float* o = g_xph + ((size_t)t * B_ + bb) * 16;
#pragma unroll
        for (int n = 0; n < 13; n++) o[n] = acc[n] + bs[n];
    }
}

// ---------------- 4) head recurrences (3 tiny forward scans) ----------------
__global__ void head_rnn_kernel(
    const float* __restrict__ wi_hh,
    const float* __restrict__ wf_hh,
    const float* __restrict__ wc_hh,
    float* __restrict__ out)
{
    int hid = blockIdx.x % 3;
    int b   = blockIdx.x / 3;
    int lane = threadIdx.x;
    int C, off;
    size_t outoff;
    const float* Whh;
    if (hid == 0)      { C = 3; off = 0; outoff = 0;                         Whh = wi_hh; }
    else if (hid == 1) { C = 5; off = 3; outoff = (size_t)B_*T_*3;           Whh = wf_hh; }
    else               { C = 5; off = 8; outoff = (size_t)B_*T_*3 + (size_t)B_*T_*5; Whh = wc_hh; }

    float w[5] = {0,0,0,0,0};
    if (lane < C)
        for (int k = 0; k < C; k++) w[k] = Whh[lane*C + k];

    float h = 0.f;
    float* ob = out + outoff + (size_t)b * T_ * C;
    float xv = (lane < C) ? g_xph[((size_t)0 * B_ + b) * 16 + off + lane] : 0.f;
    for (int t = 0; t < T_; t++) {
        float xn = 0.f;
        if (t + 1 < T_ && lane < C)
            xn = g_xph[((size_t)(t+1) * B_ + b) * 16 + off + lane];
        float h0 = __shfl_sync(0xffffffff, h, 0);
        float h1 = __shfl_sync(0xffffffff, h, 1);
        float h2 = __shfl_sync(0xffffffff, h, 2);
        float h3 = __shfl_sync(0xffffffff, h, 3);
        float h4 = __shfl_sync(0xffffffff, h, 4);
        float acc = xv + h0*w[0] + h1*w[1] + h2*w[2] + h3*w[3] + h4*w[4];
        h = ftanh(acc);
        if (lane < C) ob[(size_t)t * C + lane] = h;
        xv = xn;
    }
}

// ---------------- launch ----------------
extern "C" void kernel_launch(void* const* d_in, const int* in_sizes, int n_in,
                              void* d_out, int out_size) {
    const int*   tokens = (const int*)  d_in[0];
    const float* emb    = (const float*)d_in[1];
    const float* w_ih   = (const float*)d_in[2];   // [2][2][256][512]
    const float* w_hh   = (const float*)d_in[3];   // [2][2][256][256]
    const float* b_ih   = (const float*)d_in[4];   // [2][2][256]
    const float* b_hh   = (const float*)d_in[5];
    const float* iw_ih  = (const float*)d_in[6];
    const float* iw_hh  = (const float*)d_in[7];
    const float* ib_ih  = (const float*)d_in[8];
    const float* ib_hh  = (const float*)d_in[9];
    const float* fw_ih  = (const float*)d_in[10];
    const float* fw_hh  = (const float*)d_in[11];
    const float* fb_ih  = (const float*)d_in[12];
    const float* fb_hh  = (const float*)d_in[13];
    const float* cw_ih  = (const float*)d_in[14];
    const float* cw_hh  = (const float*)d_in[15];
    const float* cb_ih  = (const float*)d_in[16];
    const float* cb_hh  = (const float*)d_in[17];
    float* out = (float*)d_out;

    const int rnn_smem = (WSH4 * 512 * 4 + 2 * HBUF) * 4;   // ~67.6 KB
    cudaFuncSetAttribute(rnn_layer_kernel,
                         cudaFuncAttributeMaxDynamicSharedMemorySize, rnn_smem);

    // layer 0: projection (fused embedding gather) + scan
    gemm_xp_kernel<<<dim3(M_/128, 512/128), 256>>>(0, tokens, emb,
                                                   w_ih, b_ih, b_hh);
    rnn_layer_kernel<<<B_ * 2, 512, rnn_smem>>>(w_hh, 0);

    // layer 1: projection + scan
    gemm_xp_kernel<<<dim3(M_/128, 512/128), 256>>>(1, tokens, emb,
                                                   w_ih + 2*H_*E_,
                                                   b_ih + 2*H_, b_hh + 2*H_);
    rnn_layer_kernel<<<B_ * 2, 512, rnn_smem>>>(w_hh + 2*H_*H_, 1);

    // head projections (with ReLU on the fly)
    head_xp_kernel<<<M_/8, 256>>>(iw_ih, ib_ih, ib_hh,
                                  fw_ih, fb_ih, fb_hh,
                                  cw_ih, cb_ih, cb_hh);

    // head scans -> final output
    head_rnn_kernel<<<B_ * 3, 32>>>(iw_hh, fw_hh, cw_hh, out);
}